// round 2
// baseline (speedup 1.0000x reference)
#include <cuda_runtime.h>

#define B_ 8
#define N_ 1024
#define C_ 64

// Scratch for Chebyshev recurrence (allocation-free rule -> __device__ globals)
__device__ float g_Z1[B_ * N_ * C_];
__device__ float g_Z2[B_ * N_ * C_];
__device__ float g_Z3[B_ * N_ * C_];

// Shared layout (bytes):
//   main loop:  Ls[16][68] (transposed L tile), Bs[16][68]
//   epilogue :  Zs[64][68], Th[64][64]
// max = 64*68*4 + 64*64*4 = 33792 B  (< 48KB static)
#define SMEM_FLOATS 8448

__device__ __forceinline__ void theta_accum(const float* Zs, const float* Th,
                                            int trow, int tcol, float o[4][4]) {
    #pragma unroll 8
    for (int c = 0; c < 64; c++) {
        float a0 = Zs[(trow + 0) * 68 + c];
        float a1 = Zs[(trow + 1) * 68 + c];
        float a2 = Zs[(trow + 2) * 68 + c];
        float a3 = Zs[(trow + 3) * 68 + c];
        float4 t = *(const float4*)&Th[c * 64 + tcol];
        o[0][0] += a0 * t.x; o[0][1] += a0 * t.y; o[0][2] += a0 * t.z; o[0][3] += a0 * t.w;
        o[1][0] += a1 * t.x; o[1][1] += a1 * t.y; o[1][2] += a1 * t.z; o[1][3] += a1 * t.w;
        o[2][0] += a2 * t.x; o[2][1] += a2 * t.y; o[2][2] += a2 * t.z; o[2][3] += a2 * t.w;
        o[3][0] += a3 * t.x; o[3][1] += a3 * t.y; o[3][2] += a3 * t.z; o[3][3] += a3 * t.w;
    }
}

// One Chebyshev pass for rows [m0, m0+64) of batch b:
//   C      = L[b] @ Bin[b]            (64 x 64 tile, K = 1024)
//   Znext  = alpha*C - (FIRST ? 0 : Sub)
//   Zout   = Znext
//   out    = (FIRST ? x@th0 + Znext@thK : out + Znext@thK)
template <bool FIRST>
__global__ __launch_bounds__(256)
void cheb_pass(const float* __restrict__ L,
               const float* __restrict__ Bin,
               const float* __restrict__ Sub,
               const float* __restrict__ x,
               const float* __restrict__ thK,
               const float* __restrict__ th0,
               float* __restrict__ Zout,
               float* __restrict__ out,
               float alpha) {
    __shared__ __align__(16) float sraw[SMEM_FLOATS];
    float* Ls = sraw;              // [16][68], Ls[k][m] (transposed)
    float* Bs = sraw + 16 * 68;    // [16][68], Bs[k][n]

    const int tid  = threadIdx.x;
    const int b    = blockIdx.y;
    const int m0   = blockIdx.x * 64;

    const int trow = (tid >> 4) * 4;   // 0..60
    const int tcol = (tid & 15) * 4;   // 0..60

    const int lr = tid >> 2;           // 0..63   (L row within tile)
    const int lk = (tid & 3) * 4;      // 0,4,8,12 (k offset within chunk)
    const int bk = tid >> 4;           // 0..15   (B k within chunk)
    const int bn = (tid & 15) * 4;     // 0..60

    const float* Lb = L   + ((size_t)b * N_ + m0) * N_;
    const float* Bb = Bin + (size_t)b * N_ * C_;

    float acc[4][4];
    #pragma unroll
    for (int i = 0; i < 4; i++)
        #pragma unroll
        for (int j = 0; j < 4; j++) acc[i][j] = 0.f;

    // ---- main GEMM loop: C = L @ Bin, K = 1024 in chunks of 16 ----
    float4 rL = *(const float4*)(Lb + (size_t)lr * N_ + lk);
    float4 rB = *(const float4*)(Bb + (size_t)bk * C_ + bn);

    Ls[(lk + 0) * 68 + lr] = rL.x;
    Ls[(lk + 1) * 68 + lr] = rL.y;
    Ls[(lk + 2) * 68 + lr] = rL.z;
    Ls[(lk + 3) * 68 + lr] = rL.w;
    *(float4*)&Bs[bk * 68 + bn] = rB;
    __syncthreads();

    const int NCH = N_ / 16;  // 64
    for (int ch = 0; ch < NCH; ch++) {
        if (ch + 1 < NCH) {
            const int k0 = (ch + 1) * 16;
            rL = *(const float4*)(Lb + (size_t)lr * N_ + k0 + lk);
            rB = *(const float4*)(Bb + (size_t)(k0 + bk) * C_ + bn);
        }
        #pragma unroll
        for (int kk = 0; kk < 16; kk++) {
            float4 a = *(const float4*)&Ls[kk * 68 + trow];
            float4 v = *(const float4*)&Bs[kk * 68 + tcol];
            acc[0][0] += a.x * v.x; acc[0][1] += a.x * v.y; acc[0][2] += a.x * v.z; acc[0][3] += a.x * v.w;
            acc[1][0] += a.y * v.x; acc[1][1] += a.y * v.y; acc[1][2] += a.y * v.z; acc[1][3] += a.y * v.w;
            acc[2][0] += a.z * v.x; acc[2][1] += a.z * v.y; acc[2][2] += a.z * v.z; acc[2][3] += a.z * v.w;
            acc[3][0] += a.w * v.x; acc[3][1] += a.w * v.y; acc[3][2] += a.w * v.z; acc[3][3] += a.w * v.w;
        }
        __syncthreads();
        if (ch + 1 < NCH) {
            Ls[(lk + 0) * 68 + lr] = rL.x;
            Ls[(lk + 1) * 68 + lr] = rL.y;
            Ls[(lk + 2) * 68 + lr] = rL.z;
            Ls[(lk + 3) * 68 + lr] = rL.w;
            *(float4*)&Bs[bk * 68 + bn] = rB;
        }
        __syncthreads();
    }

    // ---- Znext = alpha*C - Sub ; write to Zout ----
    float zn[4][4];
    if (FIRST) {
        #pragma unroll
        for (int i = 0; i < 4; i++)
            #pragma unroll
            for (int j = 0; j < 4; j++) zn[i][j] = acc[i][j];
    } else {
        const float* Sb = Sub + ((size_t)b * N_ + m0) * C_;
        #pragma unroll
        for (int i = 0; i < 4; i++) {
            float4 s = *(const float4*)(Sb + (size_t)(trow + i) * C_ + tcol);
            zn[i][0] = alpha * acc[i][0] - s.x;
            zn[i][1] = alpha * acc[i][1] - s.y;
            zn[i][2] = alpha * acc[i][2] - s.z;
            zn[i][3] = alpha * acc[i][3] - s.w;
        }
    }
    {
        float* Zo = Zout + ((size_t)b * N_ + m0) * C_;
        #pragma unroll
        for (int i = 0; i < 4; i++) {
            float4 z = make_float4(zn[i][0], zn[i][1], zn[i][2], zn[i][3]);
            *(float4*)(Zo + (size_t)(trow + i) * C_ + tcol) = z;
        }
    }

    // ---- epilogue: out (+)= Znext @ thK  [+ x @ th0 when FIRST] ----
    float* Zs = sraw;            // [64][68]
    float* Th = sraw + 64 * 68;  // [64][64]

    #pragma unroll
    for (int i = 0; i < 4; i++) {
        float4 z = make_float4(zn[i][0], zn[i][1], zn[i][2], zn[i][3]);
        *(float4*)&Zs[(trow + i) * 68 + tcol] = z;
    }
    #pragma unroll
    for (int i = 0; i < 4; i++) {
        const int idx = i * 1024 + tid * 4;
        *(float4*)&Th[idx] = *(const float4*)(thK + idx);
    }
    __syncthreads();

    float o[4][4];
    #pragma unroll
    for (int i = 0; i < 4; i++)
        #pragma unroll
        for (int j = 0; j < 4; j++) o[i][j] = 0.f;

    theta_accum(Zs, Th, trow, tcol, o);

    if (FIRST) {
        __syncthreads();
        // stage x tile into Zs, th0 into Th
        const float* xb = x + ((size_t)b * N_ + m0) * C_;
        const int xr = tid >> 2;
        const int xc = (tid & 3) * 16;
        #pragma unroll
        for (int q = 0; q < 4; q++) {
            float4 v = *(const float4*)(xb + (size_t)xr * C_ + xc + q * 4);
            *(float4*)&Zs[xr * 68 + xc + q * 4] = v;
        }
        #pragma unroll
        for (int i = 0; i < 4; i++) {
            const int idx = i * 1024 + tid * 4;
            *(float4*)&Th[idx] = *(const float4*)(th0 + idx);
        }
        __syncthreads();
        theta_accum(Zs, Th, trow, tcol, o);
    }

    float* ob = out + ((size_t)b * N_ + m0) * C_;
    #pragma unroll
    for (int i = 0; i < 4; i++) {
        float4 v = make_float4(o[i][0], o[i][1], o[i][2], o[i][3]);
        if (!FIRST) {
            float4 cur = *(const float4*)(ob + (size_t)(trow + i) * C_ + tcol);
            v.x += cur.x; v.y += cur.y; v.z += cur.z; v.w += cur.w;
        }
        *(float4*)(ob + (size_t)(trow + i) * C_ + tcol) = v;
    }
}

extern "C" void kernel_launch(void* const* d_in, const int* in_sizes, int n_in,
                              void* d_out, int out_size) {
    (void)in_sizes; (void)n_in; (void)out_size;
    const float* x  = (const float*)d_in[0];   // [8,1024,64]
    const float* L  = (const float*)d_in[1];   // [8,1024,1024]
    const float* th = (const float*)d_in[2];   // [4,64,64]
    float* out = (float*)d_out;                // [8,1024,64]

    float *z1, *z2, *z3;
    cudaGetSymbolAddress((void**)&z1, g_Z1);
    cudaGetSymbolAddress((void**)&z2, g_Z2);
    cudaGetSymbolAddress((void**)&z3, g_Z3);

    dim3 grid(N_ / 64, B_);
    dim3 block(256);

    // Z1 = L x           ; out  = x@th0 + Z1@th1
    cheb_pass<true ><<<grid, block>>>(L, x,  nullptr, x, th + 1 * 4096, th, z1, out, 1.0f);
    // Z2 = 2 L Z1 - x    ; out += Z2@th2
    cheb_pass<false><<<grid, block>>>(L, z1, x,  nullptr, th + 2 * 4096, nullptr, z2, out, 2.0f);
    // Z3 = 2 L Z2 - Z1   ; out += Z3@th3
    cheb_pass<false><<<grid, block>>>(L, z2, z1, nullptr, th + 3 * 4096, nullptr, z3, out, 2.0f);
}

// round 4
// speedup vs baseline: 2.2570x; 2.2570x over previous
#include <cuda_runtime.h>
#include <cuda_bf16.h>
#include <cstdint>

#define B_ 8
#define N_ 1024
#define C_ 64

// ---------------- device scratch (allocation-free rule) ----------------
__device__ __nv_bfloat16 g_LH[B_ * N_ * N_];
__device__ __nv_bfloat16 g_LL[B_ * N_ * N_];
__device__ __nv_bfloat16 g_xH[B_ * N_ * C_];
__device__ __nv_bfloat16 g_xL[B_ * N_ * C_];
__device__ __nv_bfloat16 g_z1H[B_ * N_ * C_];
__device__ __nv_bfloat16 g_z1L[B_ * N_ * C_];
__device__ __nv_bfloat16 g_z2H[B_ * N_ * C_];
__device__ __nv_bfloat16 g_z2L[B_ * N_ * C_];
__device__ float         g_Z1f[B_ * N_ * C_];
__device__ __nv_bfloat16 g_thH[4 * 64 * 64];   // theta[k][ci][co] bf16-hi (row-major, as-is)
__device__ __nv_bfloat16 g_thL[4 * 64 * 64];   // bf16-lo

// ---------------- helpers ----------------
__device__ __forceinline__ uint32_t smem_u32(const void* p) {
    uint32_t a;
    asm("{ .reg .u64 t; cvta.to.shared.u64 t, %1; cvt.u32.u64 %0, t; }" : "=r"(a) : "l"(p));
    return a;
}
__device__ __forceinline__ void cp16(uint32_t d, const void* s) {
    asm volatile("cp.async.cg.shared.global [%0], [%1], 16;" :: "r"(d), "l"(s));
}
#define CP_COMMIT() asm volatile("cp.async.commit_group;" ::: "memory")

__device__ __forceinline__ void split2(float a, float b, uint32_t& hi, uint32_t& lo) {
    __nv_bfloat16 ha = __float2bfloat16(a), hb = __float2bfloat16(b);
    hi = (uint32_t)__bfloat16_as_ushort(ha) | ((uint32_t)__bfloat16_as_ushort(hb) << 16);
    __nv_bfloat16 la = __float2bfloat16(a - __bfloat162float(ha));
    __nv_bfloat16 lb = __float2bfloat16(b - __bfloat162float(hb));
    lo = (uint32_t)__bfloat16_as_ushort(la) | ((uint32_t)__bfloat16_as_ushort(lb) << 16);
}

#define LDSM4(R, A) asm volatile( \
    "ldmatrix.sync.aligned.m8n8.x4.shared.b16 {%0,%1,%2,%3}, [%4];" \
    : "=r"((R)[0]), "=r"((R)[1]), "=r"((R)[2]), "=r"((R)[3]) : "r"(A))
#define LDSM4T(R, A) asm volatile( \
    "ldmatrix.sync.aligned.m8n8.x4.trans.shared.b16 {%0,%1,%2,%3}, [%4];" \
    : "=r"((R)[0]), "=r"((R)[1]), "=r"((R)[2]), "=r"((R)[3]) : "r"(A))
#define MMA16816(D, A, B0, B1) asm volatile( \
    "mma.sync.aligned.m16n8k16.row.col.f32.bf16.bf16.f32 " \
    "{%0,%1,%2,%3},{%4,%5,%6,%7},{%8,%9},{%0,%1,%2,%3};" \
    : "+f"((D)[0]), "+f"((D)[1]), "+f"((D)[2]), "+f"((D)[3]) \
    : "r"((A)[0]), "r"((A)[1]), "r"((A)[2]), "r"((A)[3]), "r"(B0), "r"(B1))

// 64x(32 n-cols per warp) x K=64 block of bf16-split MMAs.
// A tiles (hi/lo): smem [64 rows][64 k] bf16, 128B rows, SW128 (seg ^= row&7)
// B tiles (hi/lo): smem [64 k ][64 n] bf16, 128B rows, SW128
__device__ __forceinline__ void mma_block64(
    uint32_t aH, uint32_t aL, uint32_t bH, uint32_t bL,
    int wm, int wn, int lane, float acc[4][4]) {
    const int tile = lane >> 3, tl = lane & 7;
    const int arow = wm * 16 + ((tile & 1) << 3) + tl;
    const uint32_t arb = (uint32_t)arow * 128;
    const int arx = arow & 7;
    const int aks0 = tile >> 1;                 // + kk*2
    const int krl = ((tile & 1) << 3) + tl;     // + kk*16
    const int bs0 = wn * 4 + (tile >> 1);       // + p*2
    #pragma unroll
    for (int kk = 0; kk < 4; kk++) {
        uint32_t aso = arb + (uint32_t)(((aks0 + kk * 2) ^ arx) << 4);
        uint32_t AH4[4], AL4[4];
        LDSM4(AH4, aH + aso);
        LDSM4(AL4, aL + aso);
        const int kr = kk * 16 + krl;
        const int krx = kr & 7;
        const uint32_t krb = (uint32_t)kr * 128;
        uint32_t bso0 = krb + (uint32_t)(((bs0 + 0) ^ krx) << 4);
        uint32_t bso1 = krb + (uint32_t)(((bs0 + 2) ^ krx) << 4);
        uint32_t BH0[4], BH1[4], BL0[4], BL1[4];
        LDSM4T(BH0, bH + bso0);
        LDSM4T(BH1, bH + bso1);
        LDSM4T(BL0, bL + bso0);
        LDSM4T(BL1, bL + bso1);
        MMA16816(acc[0], AH4, BH0[0], BH0[1]);
        MMA16816(acc[1], AH4, BH0[2], BH0[3]);
        MMA16816(acc[2], AH4, BH1[0], BH1[1]);
        MMA16816(acc[3], AH4, BH1[2], BH1[3]);
        MMA16816(acc[0], AH4, BL0[0], BL0[1]);
        MMA16816(acc[1], AH4, BL0[2], BL0[3]);
        MMA16816(acc[2], AH4, BL1[0], BL1[1]);
        MMA16816(acc[3], AH4, BL1[2], BL1[3]);
        MMA16816(acc[0], AL4, BH0[0], BH0[1]);
        MMA16816(acc[1], AL4, BH0[2], BH0[3]);
        MMA16816(acc[2], AL4, BH1[0], BH1[1]);
        MMA16816(acc[3], AL4, BH1[2], BH1[3]);
    }
}

// ---------------- prep: fp32 -> bf16 hi/lo split (elementwise) ----------------
__global__ __launch_bounds__(256) void split_k(const float4* __restrict__ s,
                                               uint2* __restrict__ h,
                                               uint2* __restrict__ l, int n4) {
    for (int i = blockIdx.x * blockDim.x + threadIdx.x; i < n4; i += gridDim.x * blockDim.x) {
        float4 v = s[i];
        uint32_t h0, l0, h1, l1;
        split2(v.x, v.y, h0, l0);
        split2(v.z, v.w, h1, l1);
        h[i] = make_uint2(h0, h1);
        l[i] = make_uint2(l0, l1);
    }
}

// ---------------- main pass kernel ----------------
#define STG    32768
#define O_ZH   98304
#define O_ZL   (98304 + 8192)
#define O_TH   (98304 + 16384)
#define O_TL   (98304 + 24576)
#define O_XH   (98304 + 32768)
#define O_XL   (98304 + 40960)
#define O_T0H  (98304 + 49152)
#define O_T0L  (98304 + 57344)
#define SMEMSZ (98304 + 65536)

template <int PASS>
__global__ void __launch_bounds__(256, 1) cheb(
    const __nv_bfloat16* __restrict__ LH, const __nv_bfloat16* __restrict__ LL,
    const __nv_bfloat16* __restrict__ BHg, const __nv_bfloat16* __restrict__ BLg,
    const float* __restrict__ Sub,
    const __nv_bfloat16* __restrict__ thH, const __nv_bfloat16* __restrict__ thL,
    const __nv_bfloat16* __restrict__ xH, const __nv_bfloat16* __restrict__ xL,
    float* __restrict__ Zf,
    __nv_bfloat16* __restrict__ ZoH, __nv_bfloat16* __restrict__ ZoL,
    float* __restrict__ out) {

    extern __shared__ char smem[];
    const uint32_t sb = smem_u32(smem);
    const int tid = threadIdx.x, lane = tid & 31, wid = tid >> 5;
    const int wm = wid & 3, wn = wid >> 2;
    const int b = blockIdx.y, m0 = blockIdx.x * 64;

    const __nv_bfloat16* ApH = LH + ((size_t)(b * N_ + m0)) * N_;
    const __nv_bfloat16* ApL = LL + ((size_t)(b * N_ + m0)) * N_;
    const __nv_bfloat16* BpH = BHg + (size_t)b * N_ * C_;
    const __nv_bfloat16* BpL = BLg + (size_t)b * N_ * C_;

    auto load_chunk = [&](int k0, uint32_t st) {
        #pragma unroll
        for (int i = 0; i < 2; i++) {
            const int idx = tid + i * 256;
            const int row = idx >> 3, seg = idx & 7;
            const uint32_t so = (uint32_t)row * 128 + (uint32_t)((seg ^ (row & 7)) << 4);
            cp16(st + so,         ApH + (size_t)row * N_ + k0 + seg * 8);
            cp16(st + 8192 + so,  ApL + (size_t)row * N_ + k0 + seg * 8);
            cp16(st + 16384 + so, BpH + (size_t)(k0 + row) * C_ + seg * 8);
            cp16(st + 24576 + so, BpL + (size_t)(k0 + row) * C_ + seg * 8);
        }
        CP_COMMIT();
    };

    float acc[4][4] = {};
    load_chunk(0, sb);
    load_chunk(64, sb + STG);

    for (int ch = 0; ch < 16; ch++) {
        if (ch < 15) asm volatile("cp.async.wait_group 1;" ::: "memory");
        else         asm volatile("cp.async.wait_group 0;" ::: "memory");
        __syncthreads();
        const uint32_t st = sb + (uint32_t)(ch % 3) * STG;
        mma_block64(st, st + 8192, st + 16384, st + 24576, wm, wn, lane, acc);
        if (ch + 2 < 16)
            load_chunk((ch + 2) * 64, sb + (uint32_t)((ch + 2) % 3) * STG);
    }

    // ---- zn = alpha*acc - Sub ----
    const int crow = wm * 16 + (lane >> 2);
    const int ccol = wn * 32 + 2 * (lane & 3);
    float zn[4][4];
    if (PASS == 1) {
        #pragma unroll
        for (int j = 0; j < 4; j++)
            #pragma unroll
            for (int q = 0; q < 4; q++) zn[j][q] = acc[j][q];
    } else {
        const float* Sb = Sub + ((size_t)(b * N_ + m0)) * C_;
        #pragma unroll
        for (int j = 0; j < 4; j++) {
            float2 s0 = *(const float2*)(Sb + (size_t)crow * C_ + ccol + j * 8);
            float2 s1 = *(const float2*)(Sb + (size_t)(crow + 8) * C_ + ccol + j * 8);
            zn[j][0] = 2.f * acc[j][0] - s0.x;
            zn[j][1] = 2.f * acc[j][1] - s0.y;
            zn[j][2] = 2.f * acc[j][2] - s1.x;
            zn[j][3] = 2.f * acc[j][3] - s1.y;
        }
    }

    // zn -> smem (bf16 hi/lo, SW128 rows)
    #pragma unroll
    for (int j = 0; j < 4; j++) {
        const int seg = wn * 4 + j;
        const int off = (lane & 3) * 4;
        #pragma unroll
        for (int h = 0; h < 2; h++) {
            const int row = crow + h * 8;
            uint32_t hi, lo;
            split2(zn[j][2 * h], zn[j][2 * h + 1], hi, lo);
            const uint32_t so = (uint32_t)row * 128 + (uint32_t)((seg ^ (row & 7)) << 4) + off;
            *(uint32_t*)(smem + O_ZH + so) = hi;
            *(uint32_t*)(smem + O_ZL + so) = lo;
        }
    }
    if (PASS == 1) {  // z1 fp32 for pass3's Sub
        float* Zb = Zf + ((size_t)(b * N_ + m0)) * C_;
        #pragma unroll
        for (int j = 0; j < 4; j++) {
            *(float2*)(Zb + (size_t)crow * C_ + ccol + j * 8)       = make_float2(zn[j][0], zn[j][1]);
            *(float2*)(Zb + (size_t)(crow + 8) * C_ + ccol + j * 8) = make_float2(zn[j][2], zn[j][3]);
        }
    }

    // stage theta (and x, theta0 for pass 1)
    const __nv_bfloat16* tHk = thH + PASS * 4096;
    const __nv_bfloat16* tLk = thL + PASS * 4096;
    #pragma unroll
    for (int i = 0; i < 2; i++) {
        const int idx = tid + i * 256;
        const int row = idx >> 3, seg = idx & 7;
        const uint32_t so = (uint32_t)row * 128 + (uint32_t)((seg ^ (row & 7)) << 4);
        *(uint4*)(smem + O_TH + so) = *(const uint4*)(tHk + row * 64 + seg * 8);
        *(uint4*)(smem + O_TL + so) = *(const uint4*)(tLk + row * 64 + seg * 8);
        if (PASS == 1) {
            *(uint4*)(smem + O_XH + so) = *(const uint4*)(xH + ((size_t)(b * N_ + m0 + row)) * C_ + seg * 8);
            *(uint4*)(smem + O_XL + so) = *(const uint4*)(xL + ((size_t)(b * N_ + m0 + row)) * C_ + seg * 8);
            *(uint4*)(smem + O_T0H + so) = *(const uint4*)(thH + row * 64 + seg * 8);
            *(uint4*)(smem + O_T0L + so) = *(const uint4*)(thL + row * 64 + seg * 8);
        }
    }
    __syncthreads();

    // zn (hi/lo) -> global row-major [N][C]: next pass's B operand, no transpose
    if (PASS < 3) {
        #pragma unroll
        for (int i = 0; i < 2; i++) {
            const int idx = tid + i * 256;
            const int row = idx >> 3, seg = idx & 7;
            const uint32_t so = (uint32_t)row * 128 + (uint32_t)((seg ^ (row & 7)) << 4);
            *(uint4*)(ZoH + ((size_t)(b * N_ + m0 + row)) * C_ + seg * 8) = *(const uint4*)(smem + O_ZH + so);
            *(uint4*)(ZoL + ((size_t)(b * N_ + m0 + row)) * C_ + seg * 8) = *(const uint4*)(smem + O_ZL + so);
        }
    }

    // theta epilogue on tensor cores: o = zn@theta[PASS] (+ x@theta0 for PASS 1)
    float o[4][4] = {};
    mma_block64(sb + O_ZH, sb + O_ZL, sb + O_TH, sb + O_TL, wm, wn, lane, o);
    if (PASS == 1)
        mma_block64(sb + O_XH, sb + O_XL, sb + O_T0H, sb + O_T0L, wm, wn, lane, o);

    float* ob = out + ((size_t)(b * N_ + m0)) * C_;
    #pragma unroll
    for (int j = 0; j < 4; j++) {
        float2 v0 = make_float2(o[j][0], o[j][1]);
        float2 v1 = make_float2(o[j][2], o[j][3]);
        float* p0 = ob + (size_t)crow * C_ + ccol + j * 8;
        float* p1 = ob + (size_t)(crow + 8) * C_ + ccol + j * 8;
        if (PASS > 1) {
            float2 c0 = *(const float2*)p0, c1 = *(const float2*)p1;
            v0.x += c0.x; v0.y += c0.y; v1.x += c1.x; v1.y += c1.y;
        }
        *(float2*)p0 = v0;
        *(float2*)p1 = v1;
    }
}

extern "C" void kernel_launch(void* const* d_in, const int* in_sizes, int n_in,
                              void* d_out, int out_size) {
    (void)in_sizes; (void)n_in; (void)out_size;
    const float* x  = (const float*)d_in[0];   // [8,1024,64]
    const float* L  = (const float*)d_in[1];   // [8,1024,1024]
    const float* th = (const float*)d_in[2];   // [4,64,64]
    float* out = (float*)d_out;                // [8,1024,64]

    __nv_bfloat16 *lh, *ll, *xh, *xl, *z1h, *z1l, *z2h, *z2l, *thh, *thl;
    float* z1f;
    cudaGetSymbolAddress((void**)&lh, g_LH);
    cudaGetSymbolAddress((void**)&ll, g_LL);
    cudaGetSymbolAddress((void**)&xh, g_xH);
    cudaGetSymbolAddress((void**)&xl, g_xL);
    cudaGetSymbolAddress((void**)&z1h, g_z1H);
    cudaGetSymbolAddress((void**)&z1l, g_z1L);
    cudaGetSymbolAddress((void**)&z2h, g_z2H);
    cudaGetSymbolAddress((void**)&z2l, g_z2L);
    cudaGetSymbolAddress((void**)&thh, g_thH);
    cudaGetSymbolAddress((void**)&thl, g_thL);
    cudaGetSymbolAddress((void**)&z1f, g_Z1f);

    static bool attr_done = false;
    if (!attr_done) {
        cudaFuncSetAttribute(cheb<1>, cudaFuncAttributeMaxDynamicSharedMemorySize, SMEMSZ);
        cudaFuncSetAttribute(cheb<2>, cudaFuncAttributeMaxDynamicSharedMemorySize, SMEMSZ);
        cudaFuncSetAttribute(cheb<3>, cudaFuncAttributeMaxDynamicSharedMemorySize, SMEMSZ);
        attr_done = true;
    }

    // prep: fp32 -> bf16 hi/lo
    split_k<<<2048, 256>>>((const float4*)L, (uint2*)lh, (uint2*)ll, B_ * N_ * N_ / 4);
    split_k<<<512, 256>>>((const float4*)x, (uint2*)xh, (uint2*)xl, B_ * N_ * C_ / 4);
    split_k<<<16, 256>>>((const float4*)th, (uint2*)thh, (uint2*)thl, 4 * 64 * 64 / 4);

    dim3 grid(16, 8);
    // pass1: z1 = L x ; out  = x@th0 + z1@th1 ; side: z1f, z1 hi/lo
    cheb<1><<<grid, 256, SMEMSZ>>>(lh, ll, xh, xl, nullptr, thh, thl, xh, xl,
                                   z1f, z1h, z1l, out);
    // pass2: z2 = 2 L z1 - x ; out += z2@th2 ; side: z2 hi/lo
    cheb<2><<<grid, 256, SMEMSZ>>>(lh, ll, z1h, z1l, x, thh, thl, xh, xl,
                                   nullptr, z2h, z2l, out);
    // pass3: z3 = 2 L z2 - z1 ; out += z3@th3
    cheb<3><<<grid, 256, SMEMSZ>>>(lh, ll, z2h, z2l, z1f, thh, thl, xh, xl,
                                   nullptr, z1h, z1l, out);
}